// round 11
// baseline (speedup 1.0000x reference)
#include <cuda_runtime.h>
#include <cuda_bf16.h>
#include <cuda_fp16.h>

// Fixed shapes from setup_inputs: structure int32[32,32,32,32], PS=4
#define BB 32
#define DD 32
#define HH 32
#define WW 32
#define SLABS_PER_BLOCK 2
#define GRID_BLOCKS 1024               // 2048 slabs / 2
#define PATCHES_PER_BLOCK 16
#define TOTAL_PATCHES 16384
#define AIR0 102
#define AIR1 576
#define AIR2 3352
#define BIAS16 0x4000                  // forces fp16-normal bit patterns
#define BIAS32 0x40004000u
#define FP_SCALE 4294967296.0          // 2^32 fixed-point scale for deterministic atomics

// Zero-initialized at module load; last block resets them (graph-replay safe).
__device__ unsigned long long g_acc = 0ULL;
__device__ unsigned int g_ticket = 0u;

// Two compares + two accumulates in 2 instructions, one per pipe:
//   set.eq.f16x2 (alu: HSET2) + add.rn.f16x2 (fma: HADD2).
// Biased tokens are normal fp16 values => fp16 equality == bit equality.
#define SETEQ_ACC(acc, u, vv) \
    asm("{.reg .b32 t; set.eq.f16x2.f16x2 t, %1, %2; add.rn.f16x2 %0, %0, t;}" \
        : "+r"(acc) : "r"(u), "r"(vv))

// all 4 probes vs one packed tile register (8 compares, 8 inst)
#define CMP_U32(u) do { \
    SETEQ_ACC(acc0, u, vv0); SETEQ_ACC(acc1, u, vv1); \
    SETEQ_ACC(acc2, u, vv2); SETEQ_ACC(acc3, u, vv3); \
} while (0)

__device__ __forceinline__ unsigned prmt(unsigned a, unsigned b, unsigned sel) {
    unsigned d;
    asm("prmt.b32 %0, %1, %2, %3;" : "=r"(d) : "r"(a), "r"(b), "r"(sel));
    return d;
}

// f16x2 accumulator -> exact count as float (counts <= 64 are exact in fp16)
__device__ __forceinline__ float h2_countf(unsigned acc) {
    const __half2 h = *(const __half2*)&acc;
    return __low2float(h) + __high2float(h);
}

// 256 threads, 16 patches/block (two 4x4x32 slabs), 4 tokens/thread.
// Patch staged once to smem as packed u16, then ALL 8 LDS.128 are issued
// back-to-back (MLP=8) into registers; the 256-inst compare core runs with
// zero memory operations and 8 independent dependency chains.
__global__ __launch_bounds__(256)
void patch_entropy_fused_kernel(const int* __restrict__ s, float* __restrict__ out) {
    // 16 patches x 36 u32 stride (32 data + 4 pad = 144B, 16B-aligned)
    __shared__ unsigned sm32[PATCHES_PER_BLOCK * 36];
    __shared__ float red_ent[8];

    const int tid  = threadIdx.x;
    const int wid  = tid >> 5;
    const int lane = tid & 31;

    // geometry: patch pp (0..15), 16 threads per patch, thread owns 4 tokens
    const int pp = tid >> 4;
    const int q  = tid & 15;
    const int d  = q >> 2;
    const int h  = q & 3;
    const int w4 = pp & 7;
    const int gslab = blockIdx.x * SLABS_PER_BLOCK + (pp >> 3);
    const int b  = gslab >> 6;
    const int pd = (gslab >> 3) & 7;
    const int ph = gslab & 7;
    const int base = b * (DD * HH * WW) + pd * (4 * HH * WW) + ph * (4 * WW);

    // ---- LDG.128 own 4 tokens, pack to biased u16x2, stage to smem ----
    const uint4 val = *(const uint4*)(s + base + d * (HH * WW) + h * WW + w4 * 4);
    const unsigned lo = prmt(val.x, val.y, 0x5410) | BIAS32;  // tok0|tok1<<16
    const unsigned hi = prmt(val.z, val.w, 0x5410) | BIAS32;  // tok2|tok3<<16
    *(uint2*)&sm32[pp * 36 + 2 * q] = make_uint2(lo, hi);

    // probes + air flags computed while the barrier drains
    const unsigned vv0 = prmt(lo, lo, 0x1010);
    const unsigned vv1 = prmt(lo, lo, 0x3232);
    const unsigned vv2 = prmt(hi, hi, 0x1010);
    const unsigned vv3 = prmt(hi, hi, 0x3232);

    const int t0 = (int)(lo & 0xFFFFu);
    const int t1 = (int)(lo >> 16);
    const int t2 = (int)(hi & 0xFFFFu);
    const int t3 = (int)(hi >> 16);
    const int a0 = (t0 == (AIR0 | BIAS16)) | (t0 == (AIR1 | BIAS16)) | (t0 == (AIR2 | BIAS16));
    const int a1 = (t1 == (AIR0 | BIAS16)) | (t1 == (AIR1 | BIAS16)) | (t1 == (AIR2 | BIAS16));
    const int a2 = (t2 == (AIR0 | BIAS16)) | (t2 == (AIR1 | BIAS16)) | (t2 == (AIR2 | BIAS16));
    const int a3 = (t3 == (AIR0 | BIAS16)) | (t3 == (AIR1 | BIAS16)) | (t3 == (AIR2 | BIAS16));
    const int na = (4 - a0 - a1 - a2 - a3);

    __syncthreads();

    // ---- hoist the WHOLE patch into registers: 8x LDS.128, MLP=8 ----
    const uint4* pb4 = (const uint4*)&sm32[pp * 36];
    const uint4 T0 = pb4[0], T1 = pb4[1], T2 = pb4[2], T3 = pb4[3];
    const uint4 T4 = pb4[4], T5 = pb4[5], T6 = pb4[6], T7 = pb4[7];

    // ---- 256-inst pure-register compare core (HSET2/HADD2, 2 pipes) ----
    unsigned acc0 = 0, acc1 = 0, acc2 = 0, acc3 = 0;
    CMP_U32(T0.x); CMP_U32(T0.y); CMP_U32(T0.z); CMP_U32(T0.w);
    CMP_U32(T1.x); CMP_U32(T1.y); CMP_U32(T1.z); CMP_U32(T1.w);
    CMP_U32(T2.x); CMP_U32(T2.y); CMP_U32(T2.z); CMP_U32(T2.w);
    CMP_U32(T3.x); CMP_U32(T3.y); CMP_U32(T3.z); CMP_U32(T3.w);
    CMP_U32(T4.x); CMP_U32(T4.y); CMP_U32(T4.z); CMP_U32(T4.w);
    CMP_U32(T5.x); CMP_U32(T5.y); CMP_U32(T5.z); CMP_U32(T5.w);
    CMP_U32(T6.x); CMP_U32(T6.y); CMP_U32(T6.z); CMP_U32(T6.w);
    CMP_U32(T7.x); CMP_U32(T7.y); CMP_U32(T7.z); CMP_U32(T7.w);

    // tot = non-air tokens in this patch (16-lane segmented reduce)
    int tot = na;
    #pragma unroll
    for (int off = 8; off > 0; off >>= 1)
        tot += __shfl_xor_sync(0xFFFFFFFFu, tot, off);

    // entropy contribution: sum over own non-air tokens of inv_tot*(log(tot)-log(c))
    float term = 0.0f;
    if (tot > 0) {
        float sl = 0.0f;
        if (!a0) sl += __logf(h2_countf(acc0));
        if (!a1) sl += __logf(h2_countf(acc1));
        if (!a2) sl += __logf(h2_countf(acc2));
        if (!a3) sl += __logf(h2_countf(acc3));
        const float totf = (float)tot;
        term = __fdividef(1.0f, totf) * fmaf((float)na, __logf(totf), -sl);
    }

    // ---- block-level sum ----
    float x = term;
    #pragma unroll
    for (int off = 16; off > 0; off >>= 1)
        x += __shfl_xor_sync(0xFFFFFFFFu, x, off);
    if (lane == 0) red_ent[wid] = x;
    __syncthreads();

    if (wid == 0) {
        float y = (lane < 8) ? red_ent[lane] : 0.0f;
        #pragma unroll
        for (int off = 4; off > 0; off >>= 1)
            y += __shfl_xor_sync(0xFFFFFFFFu, y, off);
        if (lane == 0) {
            // fixed-point accumulate: integer atomics are order-invariant => deterministic
            const unsigned long long qv =
                (unsigned long long)(long long)((double)y * FP_SCALE);
            atomicAdd(&g_acc, qv);
            __threadfence();
            const unsigned int old = atomicAdd(&g_ticket, 1u);
            if (old == GRID_BLOCKS - 1) {
                const unsigned long long a = atomicAdd(&g_acc, 0ULL);
                const double total = (double)a / FP_SCALE;
                out[0] = (float)(total / ((double)TOTAL_PATCHES + 1e-06));
                // self-clean for the next graph replay
                g_acc = 0ULL;
                g_ticket = 0u;
            }
        }
    }
}

extern "C" void kernel_launch(void* const* d_in, const int* in_sizes, int n_in,
                              void* d_out, int out_size) {
    const int* structure = (const int*)d_in[0];
    float* out = (float*)d_out;
    patch_entropy_fused_kernel<<<GRID_BLOCKS, 256>>>(structure, out);
}

// round 12
// speedup vs baseline: 1.0239x; 1.0239x over previous
#include <cuda_runtime.h>
#include <cuda_bf16.h>
#include <cuda_fp16.h>

// Fixed shapes from setup_inputs: structure int32[32,32,32,32], PS=4
#define BB 32
#define DD 32
#define HH 32
#define WW 32
#define GRID_BLOCKS 2048               // one block per 4x4x32 slab
#define PATCHES_PER_BLOCK 8
#define TOTAL_PATCHES 16384
#define AIR0 102
#define AIR1 576
#define AIR2 3352
#define BIAS16 0x4000                  // forces fp16-normal bit patterns
#define BIAS32 0x40004000u
#define FP_SCALE 4294967296.0          // 2^32 fixed-point scale
// Packed-accumulator layout: bits [0,52) fixed-point sum (+ per-block bias),
// bits [52,64) block-arrival count. One atomicAdd does sum + count at once.
#define BLK_BIAS (1ULL << 40)          // absorbs tiny negative fp rounding per block
#define CNT_ONE  (1ULL << 52)
#define SUM_MASK (CNT_ONE - 1ULL)

// Zero-initialized at module load; last block resets it (graph-replay safe).
__device__ unsigned long long g_acc = 0ULL;

// Two compares + two accumulates in 2 instructions, one per pipe:
//   set.eq.f16x2 (alu: HSET2) + add.rn.f16x2 (fma: HADD2).
// Biased tokens are normal fp16 values => fp16 equality == bit equality.
#define SETEQ_ACC(acc, u, vv) \
    asm("{.reg .b32 t; set.eq.f16x2.f16x2 t, %1, %2; add.rn.f16x2 %0, %0, t;}" \
        : "+r"(acc) : "r"(u), "r"(vv))

__device__ __forceinline__ unsigned prmt(unsigned a, unsigned b, unsigned sel) {
    unsigned d;
    asm("prmt.b32 %0, %1, %2, %3;" : "=r"(d) : "r"(a), "r"(b), "r"(sel));
    return d;
}

// half2 -> exact small-int count (counts <= 64 are exact in fp16)
__device__ __forceinline__ int h2_count(unsigned acc) {
    const __half2 h = *(const __half2*)&acc;
    const __half s = __hadd(__low2half(h), __high2half(h));
    int r;
    asm("cvt.rni.s32.f16 %0, %1;" : "=r"(r) : "h"(*(const unsigned short*)&s));
    return r;
}

// 128 threads, 8 patches/block, 4 tokens per thread; tokens staged as biased u16.
__global__ __launch_bounds__(128, 14)
void patch_entropy_fused_kernel(const int* __restrict__ s, float* __restrict__ out) {
    // patch stride 36 u32 (32 data + 4 pad = 144B): 16B-aligned, bank-spread
    __shared__ unsigned sm32[PATCHES_PER_BLOCK * 36];
    __shared__ float logtab[65];   // log(i), log(0):=0
    __shared__ float invtab[65];   // 1/i,    1/0 :=0
    __shared__ float red_ent[4];

    const int tid = threadIdx.x;

    // ---- LUT init (one-time MUFUs, off the hot path) ----
    if (tid < 65) {
        const float fi = (float)tid;
        logtab[tid] = (tid == 0) ? 0.0f : __logf(fi);
        invtab[tid] = (tid == 0) ? 0.0f : __fdividef(1.0f, fi);
    }

    // ---- coalesced int4 load of one slab; pack 4 tokens -> 2 biased u32 ----
    {
        const int d  = tid >> 5;            // 0..3
        const int h  = (tid >> 3) & 3;      // 0..3
        const int w4 = tid & 7;             // int4 within row => patch id
        const int gslab = blockIdx.x;
        const int b   = gslab >> 6;
        const int rem = gslab & 63;
        const int pd  = rem >> 3;
        const int ph  = rem & 7;
        const int base = b * (DD * HH * WW) + pd * (4 * HH * WW) + ph * (4 * WW);
        const uint4 val = *(const uint4*)(s + base + d * (HH * WW) + h * WW + w4 * 4);
        const unsigned lo = prmt(val.x, val.y, 0x5410) | BIAS32;  // tok0|tok1<<16
        const unsigned hi = prmt(val.z, val.w, 0x5410) | BIAS32;  // tok2|tok3<<16
        const int t = d * 16 + h * 4;       // first owned token index
        *(uint2*)&sm32[w4 * 36 + (t >> 1)] = make_uint2(lo, hi);
    }
    __syncthreads();

    // ---- compute: thread owns 4 consecutive tokens of patch pp ----
    const int pp = tid >> 4;    // 0..7
    const int q  = tid & 15;    // quarter-row within patch
    const unsigned* pbase = &sm32[pp * 36];
    const uint4* pbase4 = (const uint4*)pbase;

    const uint2 mine = *(const uint2*)&pbase[2 * q];
    const int t0 = (int)(mine.x & 0xFFFFu);
    const int t1 = (int)(mine.x >> 16);
    const int t2 = (int)(mine.y & 0xFFFFu);
    const int t3 = (int)(mine.y >> 16);
    const unsigned vv0 = prmt(mine.x, mine.x, 0x1010);
    const unsigned vv1 = prmt(mine.x, mine.x, 0x3232);
    const unsigned vv2 = prmt(mine.y, mine.y, 0x1010);
    const unsigned vv3 = prmt(mine.y, mine.y, 0x3232);

    const int a0 = (t0 == (AIR0 | BIAS16)) | (t0 == (AIR1 | BIAS16)) | (t0 == (AIR2 | BIAS16));
    const int a1 = (t1 == (AIR0 | BIAS16)) | (t1 == (AIR1 | BIAS16)) | (t1 == (AIR2 | BIAS16));
    const int a2 = (t2 == (AIR0 | BIAS16)) | (t2 == (AIR1 | BIAS16)) | (t2 == (AIR2 | BIAS16));
    const int a3 = (t3 == (AIR0 | BIAS16)) | (t3 == (AIR1 | BIAS16)) | (t3 == (AIR2 | BIAS16));
    const int na = (4 - a0 - a1 - a2 - a3);   // non-air among own tokens

    // tot via 4 INDEPENDENT ballots (parallel latency) instead of a serial
    // shfl-xor chain: each 16-lane segment is one patch.
    const unsigned b0 = __ballot_sync(0xFFFFFFFFu, a0);
    const unsigned b1 = __ballot_sync(0xFFFFFFFFu, a1);
    const unsigned b2 = __ballot_sync(0xFFFFFFFFu, a2);
    const unsigned b3 = __ballot_sync(0xFFFFFFFFu, a3);
    const int segsh = (tid & 16);            // 0 or 16
    const int nair = __popc((b0 >> segsh) & 0xFFFF) + __popc((b1 >> segsh) & 0xFFFF)
                   + __popc((b2 >> segsh) & 0xFFFF) + __popc((b3 >> segsh) & 0xFFFF);
    const int tot = 64 - nair;

    // occurrence counts: 8x LDS.128 broadcast, 2 compares/inst via f16x2.
    // Depth-1 software pipeline hides the 29-cycle LDS latency.
    unsigned acc0 = 0, acc1 = 0, acc2 = 0, acc3 = 0;
    uint4 u = pbase4[0];
    #pragma unroll
    for (int k = 0; k < 8; ++k) {
        const uint4 nxt = pbase4[(k + 1) & 7];   // k==7 wraps: harmless reload
        SETEQ_ACC(acc0, u.x, vv0); SETEQ_ACC(acc1, u.x, vv1);
        SETEQ_ACC(acc2, u.x, vv2); SETEQ_ACC(acc3, u.x, vv3);
        SETEQ_ACC(acc0, u.y, vv0); SETEQ_ACC(acc1, u.y, vv1);
        SETEQ_ACC(acc2, u.y, vv2); SETEQ_ACC(acc3, u.y, vv3);
        SETEQ_ACC(acc0, u.z, vv0); SETEQ_ACC(acc1, u.z, vv1);
        SETEQ_ACC(acc2, u.z, vv2); SETEQ_ACC(acc3, u.z, vv3);
        SETEQ_ACC(acc0, u.w, vv0); SETEQ_ACC(acc1, u.w, vv1);
        SETEQ_ACC(acc2, u.w, vv2); SETEQ_ACC(acc3, u.w, vv3);
        u = nxt;
    }

    const int c0 = h2_count(acc0);
    const int c1 = h2_count(acc1);
    const int c2 = h2_count(acc2);
    const int c3 = h2_count(acc3);

    // entropy contribution: sum over own non-air tokens of inv_tot*(log(tot)-log(c))
    float sl = 0.0f;
    if (!a0) sl += logtab[c0];
    if (!a1) sl += logtab[c1];
    if (!a2) sl += logtab[c2];
    if (!a3) sl += logtab[c3];
    const float term = invtab[tot] * ((float)na * logtab[tot] - sl);

    // ---- block-level sum of terms ----
    float x = term;
    #pragma unroll
    for (int off = 16; off > 0; off >>= 1)
        x += __shfl_xor_sync(0xFFFFFFFFu, x, off);
    const int wid = tid >> 5, lane = tid & 31;
    if (lane == 0) red_ent[wid] = x;
    __syncthreads();

    if (wid == 0) {
        float y = (lane < 4) ? red_ent[lane] : 0.0f;
        #pragma unroll
        for (int off = 2; off > 0; off >>= 1)
            y += __shfl_xor_sync(0xFFFFFFFFu, y, off);
        if (lane == 0) {
            // Single packed atomic: sum (biased, bits 0..51) + arrival count
            // (bits 52+). The return value of the LAST block's atomic already
            // contains every other block's contribution — no fence, no ticket,
            // no re-read. Integer adds => order-invariant => deterministic.
            const long long sfp = (long long)((double)y * FP_SCALE);
            const unsigned long long qv =
                (unsigned long long)(sfp + (long long)BLK_BIAS) | CNT_ONE;
            const unsigned long long old = atomicAdd(&g_acc, qv);
            if ((old >> 52) == (GRID_BLOCKS - 1)) {
                const unsigned long long sum52 = (old + qv) & SUM_MASK;
                const double total =
                    ((double)(long long)(sum52 - (unsigned long long)GRID_BLOCKS * BLK_BIAS))
                    / FP_SCALE;
                out[0] = (float)(total / ((double)TOTAL_PATCHES + 1e-06));
                g_acc = 0ULL;   // self-clean for the next graph replay
            }
        }
    }
}

extern "C" void kernel_launch(void* const* d_in, const int* in_sizes, int n_in,
                              void* d_out, int out_size) {
    const int* structure = (const int*)d_in[0];
    float* out = (float*)d_out;
    patch_entropy_fused_kernel<<<GRID_BLOCKS, 128>>>(structure, out);
}